// round 17
// baseline (speedup 1.0000x reference)
#include <cuda_runtime.h>
#include <cuda_bf16.h>
#include <cstdint>

// ---------------------------------------------------------------------------
// AdaptiveEMAModel. R12 best-measured baseline (vocab-table preprocess with
// 32-token occ-2 tiles; single-bar branchless scan) + R17 scan change:
// software-pipelined kn registers — next step's kn is preloaded into an
// alternate register buffer right after the barrier (its ring slot was
// written two bars earlier), so the matvec starts on ready registers.
// ---------------------------------------------------------------------------

typedef unsigned long long u64t;

__device__ __forceinline__ u64t pk2(float lo, float hi) {
    u64t r;
    asm("mov.b64 %0, {%1, %2};" : "=l"(r) : "f"(lo), "f"(hi));
    return r;
}
__device__ __forceinline__ void fma2(u64t& d, u64t a, u64t b) {
    asm("fma.rn.f32x2 %0, %1, %2, %0;" : "+l"(d) : "l"(a), "l"(b));
}
__device__ __forceinline__ float2 upk(u64t v) {
    float2 f;
    asm("mov.b64 {%0, %1}, %2;" : "=f"(f.x), "=f"(f.y) : "l"(v));
    return f;
}
__device__ __forceinline__ float hsum(u64t v) {
    float2 f = upk(v);
    return f.x + f.y;
}

#define Bn   64
#define Ln   2048
#define Hn   128
#define H2n  256
#define Vn   32000
#define NTOK (Bn * Ln)

// ------------------------- global scratch ----------------------------------
__device__ __align__(16) float g_y[(size_t)Vn * H2n];      // 32.8 MB
__device__ __align__(16) float g_part[(size_t)Vn * Hn];    // 16.4 MB
__device__ __align__(16) float g_hln[(size_t)Vn * Hn];     // 16.4 MB
__device__ __align__(16) float g_Kv[(size_t)Vn * Hn];      // raw k per vocab
__device__ __align__(16) float g_KNv[(size_t)Vn * Hn];     // normalized k
__device__ __align__(16) float g_THv[Vn];                  // (0.4*||k||)^2
__device__ __align__(16) float g_read[Bn * Hn];
__device__ __align__(16) float g_r2[Bn * Hn];
__device__ int g_is64;

// ------------------------- K0: detect seq dtype ----------------------------
__global__ void k0_detect(const unsigned int* __restrict__ sw) {
    int t = threadIdx.x;
    int nz = (sw[2 * t + 1] != 0u) ? 1 : 0;
    nz = __syncthreads_or(nz);
    if (t == 0) g_is64 = nz ? 0 : 1;
}

// ------------------------- shared GEMM core (32tok x 128out x 128red) ------
#define KVT_SMEM ((128 * 132 + 32 * 132) * 4)

__device__ __forceinline__ void gemm_core(const float* __restrict__ Wsm,
                                          const float* __restrict__ Xsm,
                                          int tg, int lane, u64t acc[4][4]) {
    const float4* W4 = (const float4*)Wsm;
    const float4* X4 = (const float4*)Xsm;
#pragma unroll
    for (int i = 0; i < 4; ++i)
#pragma unroll
        for (int j = 0; j < 4; ++j) acc[i][j] = 0ull;
#pragma unroll 4
    for (int hh = 0; hh < 32; ++hh) {
        u64t wl[4], wh[4];
#pragma unroll
        for (int j = 0; j < 4; ++j) {
            float4 wq = W4[(lane + 32 * j) * 33 + hh];
            wl[j] = pk2(wq.x, wq.y);
            wh[j] = pk2(wq.z, wq.w);
        }
#pragma unroll
        for (int i = 0; i < 4; ++i) {
            float4 xq = X4[(tg + i) * 33 + hh];
            u64t xl = pk2(xq.x, xq.y), xh = pk2(xq.z, xq.w);
#pragma unroll
            for (int j = 0; j < 4; ++j) {
                fma2(acc[i][j], xl, wl[j]);
                fma2(acc[i][j], xh, wh[j]);
            }
        }
    }
}

__device__ __forceinline__ void stage_w(float* Wsm, const float* __restrict__ src,
                                        int rstride, int tid) {
    for (int i = tid; i < 128 * 32; i += 256) {
        int r = i >> 5, c = i & 31;
        *(float4*)(Wsm + r * 132 + 4 * c) = *(const float4*)(src + (size_t)r * rstride + 4 * c);
    }
}
__device__ __forceinline__ void stage_x(float* Xsm, const float* __restrict__ src,
                                        int rstride, int tid) {
    for (int i = tid; i < 32 * 32; i += 256) {
        int tk = i >> 5, q = i & 31;
        *(float4*)(Xsm + tk * 132 + 4 * q) = *(const float4*)(src + (size_t)tk * rstride + 4 * q);
    }
}

// ------------------------- KV1: FFN layer 1 (one output half) --------------
__global__ __launch_bounds__(256, 2)
void kv1(const float* __restrict__ ew, const float* __restrict__ w1,
         const float* __restrict__ b1, int obase) {
    extern __shared__ float sm[];
    float* W = sm;
    float* X = sm + 128 * 132;

    const int tid = threadIdx.x;
    const int lane = tid & 31;
    const int tg = (tid >> 5) * 4;

    stage_w(W, w1 + (size_t)obase * 128, 128, tid);
    float bb[4];
#pragma unroll
    for (int j = 0; j < 4; ++j) bb[j] = b1[obase + lane + 32 * j];
    __syncthreads();

    for (int tile = blockIdx.x; tile < Vn / 32; tile += gridDim.x) {
        const int v0 = tile * 32;
        stage_x(X, ew + (size_t)v0 * 128, 128, tid);
        __syncthreads();

        u64t acc[4][4];
        gemm_core(W, X, tg, lane, acc);

#pragma unroll
        for (int i = 0; i < 4; ++i)
#pragma unroll
            for (int j = 0; j < 4; ++j) {
                float y = hsum(acc[i][j]) + bb[j];
                g_y[(size_t)(v0 + tg + i) * H2n + obase + lane + 32 * j] = fmaxf(y, 0.0f);
            }
        __syncthreads();
    }
}

// ------------------------- KV2a: FFN layer 2, reduction half 0 -> partial --
__global__ __launch_bounds__(256, 2)
void kv2a(const float* __restrict__ w2) {
    extern __shared__ float sm[];
    float* W = sm;
    float* X = sm + 128 * 132;

    const int tid = threadIdx.x;
    const int lane = tid & 31;
    const int tg = (tid >> 5) * 4;

    stage_w(W, w2, 256, tid);
    __syncthreads();

    for (int tile = blockIdx.x; tile < Vn / 32; tile += gridDim.x) {
        const int v0 = tile * 32;
        stage_x(X, g_y + (size_t)v0 * H2n, H2n, tid);
        __syncthreads();

        u64t acc[4][4];
        gemm_core(W, X, tg, lane, acc);

#pragma unroll
        for (int i = 0; i < 4; ++i)
#pragma unroll
            for (int j = 0; j < 4; ++j)
                g_part[(size_t)(v0 + tg + i) * Hn + lane + 32 * j] = hsum(acc[i][j]);
        __syncthreads();
    }
}

// ------------------------- KV2b: reduction half 1 + bias + residual + LN ---
__global__ __launch_bounds__(256, 2)
void kv2b(const float* __restrict__ ew, const float* __restrict__ w2,
          const float* __restrict__ b2,
          const float* __restrict__ lng, const float* __restrict__ lnb) {
    extern __shared__ float sm[];
    float* W = sm;
    float* X = sm + 128 * 132;

    const int tid = threadIdx.x;
    const int lane = tid & 31;
    const int tg = (tid >> 5) * 4;

    stage_w(W, w2 + 128, 256, tid);
    float b2r[4], gr[4], br[4];
#pragma unroll
    for (int j = 0; j < 4; ++j) {
        b2r[j] = b2[lane + 32 * j];
        gr[j] = lng[lane + 32 * j];
        br[j] = lnb[lane + 32 * j];
    }
    __syncthreads();

    for (int tile = blockIdx.x; tile < Vn / 32; tile += gridDim.x) {
        const int v0 = tile * 32;
        stage_x(X, g_y + (size_t)v0 * H2n + 128, H2n, tid);
        __syncthreads();

        u64t acc[4][4];
        gemm_core(W, X, tg, lane, acc);

#pragma unroll
        for (int i = 0; i < 4; ++i) {
            const size_t tok = (size_t)(v0 + tg + i);
            float x[4];
#pragma unroll
            for (int j = 0; j < 4; ++j)
                x[j] = hsum(acc[i][j]) + g_part[tok * Hn + lane + 32 * j]
                     + b2r[j] + ew[tok * 128 + lane + 32 * j];
            float s = x[0] + x[1] + x[2] + x[3];
#pragma unroll
            for (int off = 16; off; off >>= 1) s += __shfl_xor_sync(0xffffffffu, s, off);
            float mu = s * (1.0f / 128.0f);
            float vs = 0.0f;
#pragma unroll
            for (int j = 0; j < 4; ++j) { float dv = x[j] - mu; vs += dv * dv; }
#pragma unroll
            for (int off = 16; off; off >>= 1) vs += __shfl_xor_sync(0xffffffffu, vs, off);
            float den = sqrtf(vs * (1.0f / 128.0f) + 1e-5f);
#pragma unroll
            for (int j = 0; j < 4; ++j)
                g_hln[tok * Hn + lane + 32 * j] = (x[j] - mu) / den * gr[j] + br[j];
        }
        __syncthreads();
    }
}

// ------------------------- KV3: kproj + norm/kn/threshold ------------------
__global__ __launch_bounds__(256, 2)
void kv3(const float* __restrict__ kpw) {
    extern __shared__ float sm[];
    float* W = sm;
    float* X = sm + 128 * 132;

    const int tid = threadIdx.x;
    const int lane = tid & 31;
    const int tg = (tid >> 5) * 4;

    stage_w(W, kpw, 128, tid);
    __syncthreads();

    for (int tile = blockIdx.x; tile < Vn / 32; tile += gridDim.x) {
        const int v0 = tile * 32;
        stage_x(X, g_hln + (size_t)v0 * Hn, Hn, tid);
        __syncthreads();

        u64t acc[4][4];
        gemm_core(W, X, tg, lane, acc);

#pragma unroll
        for (int i = 0; i < 4; ++i) {
            const size_t tok = (size_t)(v0 + tg + i);
            float kv[4];
            float s = 0.0f;
#pragma unroll
            for (int j = 0; j < 4; ++j) {
                kv[j] = hsum(acc[i][j]);
                g_Kv[tok * Hn + lane + 32 * j] = kv[j];
                s += kv[j] * kv[j];
            }
#pragma unroll
            for (int off = 16; off; off >>= 1) s += __shfl_xor_sync(0xffffffffu, s, off);
            float nm = fmaxf(sqrtf(s), 1e-12f);
#pragma unroll
            for (int j = 0; j < 4; ++j)
                g_KNv[tok * Hn + lane + 32 * j] = kv[j] / nm;
            if (lane == 0) {
                float t1 = 0.4f * nm;
                g_THv[tok] = t1 * t1;
            }
        }
        __syncthreads();
    }
}

// ------------------------- K2: scan with pipelined kn registers ------------
// 64 CTAs x 256 threads. Thread pair (2r, 2r+1) owns M row r (64 cols as
// 32 f32x2 regs). Ring slot t+1's data was written at step t-1 (two bars
// earlier), so it is preloaded into an alternate register buffer right after
// this step's barrier — the matvec always starts on ready registers.
#define SCAN_STEP(T, KCUR, KNXT)                                              \
{                                                                             \
    const int t = (T);                                                        \
    const int tp = t + 3;                                                     \
    float Lnew = 0.0f;                                                        \
    if (tp < Ln - 1)       Lnew = g_KNv[(size_t)idxs[tp] * Hn + row];         \
    else if (tp == Ln - 1) Lnew = g_Kv[(size_t)idxs[Ln - 1] * Hn + row];      \
    const int tk = (tp < Ln) ? tp : Ln - 1;                                   \
    float knew = g_Kv[(size_t)idxs[tk] * Hn + row];                           \
    float thn = ths[(t + 1 < Ln) ? t + 1 : t];                                \
    if (half == 0) kns[(t + 2) & 7][pos] = Lprev;                             \
    u64t a0 = 0ull, a1 = 0ull, a2 = 0ull, a3 = 0ull;                          \
    _Pragma("unroll")                                                         \
    for (int c = 0; c < 8; ++c) {                                             \
        fma2(a0, M[4 * c],     KCUR[4 * c]);                                  \
        fma2(a1, M[4 * c + 1], KCUR[4 * c + 1]);                              \
        fma2(a2, M[4 * c + 2], KCUR[4 * c + 2]);                              \
        fma2(a3, M[4 * c + 3], KCUR[4 * c + 3]);                              \
    }                                                                         \
    float vph = (hsum(a0) + hsum(a1)) + (hsum(a2) + hsum(a3));                \
    float vp = vph + __shfl_xor_sync(0xffffffffu, vph, 1);                    \
    float d = kcur - vp;                                                      \
    float dsq = d * d;                                                        \
    dsq += __shfl_xor_sync(0xffffffffu, dsq, 2);                              \
    dsq += __shfl_xor_sync(0xffffffffu, dsq, 4);                              \
    dsq += __shfl_xor_sync(0xffffffffu, dsq, 8);                              \
    dsq += __shfl_xor_sync(0xffffffffu, dsq, 16);                             \
    if (lane == 0) red[t & 1][w] = dsq;                                       \
    __syncthreads();                                                          \
    {                                                                         \
        const float4* nx = (const float4*)(kns[(t + 1) & 7] + 68 * half);     \
        _Pragma("unroll")                                                     \
        for (int c = 0; c < 8; ++c) {                                         \
            float4 v0 = nx[2 * c];                                            \
            float4 v1 = nx[2 * c + 1];                                        \
            KNXT[4 * c]     = pk2(v0.x, v0.y);                                \
            KNXT[4 * c + 1] = pk2(v0.z, v0.w);                                \
            KNXT[4 * c + 2] = pk2(v1.x, v1.y);                                \
            KNXT[4 * c + 3] = pk2(v1.z, v1.w);                                \
        }                                                                     \
    }                                                                         \
    float4 r0 = *(const float4*)&red[t & 1][0];                               \
    float4 r1 = *(const float4*)&red[t & 1][4];                               \
    float dd = ((r0.x + r0.y) + (r0.z + r0.w)) + ((r1.x + r1.y) + (r1.z + r1.w)); \
    float s = (dd >= thc) ? d * (1.0f / 2048.0f) : 0.0f;                      \
    u64t s2 = pk2(s, s);                                                      \
    _Pragma("unroll")                                                         \
    for (int c = 0; c < 32; ++c) fma2(M[c], s2, KCUR[c]);                     \
    kcur = knx1; knx1 = knx2; knx2 = knew;                                    \
    thc = thn;                                                                \
    Lprev = Lnew;                                                             \
}

__global__ __launch_bounds__(256, 1)
void k2_scan(const void* __restrict__ seq) {
    const int b = blockIdx.x;
    const int tid = threadIdx.x;
    const int lane = tid & 31;
    const int w = tid >> 5;
    const int row = tid >> 1;
    const int half = tid & 1;

    __shared__ int   idxs[Ln];
    __shared__ float ths[Ln];
    __shared__ __align__(16) float kns[8][136];   // kn ring, slot = t & 7
    __shared__ __align__(16) float red[2][8];

    const int is64 = g_is64;
    for (int i = tid; i < Ln; i += 256) {
        long long idx = is64 ? ((const long long*)seq)[(size_t)b * Ln + i]
                             : (long long)((const int*)seq)[(size_t)b * Ln + i];
        idxs[i] = (int)idx;
        ths[i] = g_THv[idx];
    }
    __syncthreads();

    const int pos = 68 * (row >> 6) + (row & 63);
    if (half == 0) {
        kns[0][pos] = g_KNv[(size_t)idxs[0] * Hn + row];
        kns[1][pos] = g_KNv[(size_t)idxs[1] * Hn + row];
    }
    float Lprev = g_KNv[(size_t)idxs[2] * Hn + row];       // kn[2] in flight
    float kcur = g_Kv[(size_t)idxs[0] * Hn + row];
    float knx1 = g_Kv[(size_t)idxs[1] * Hn + row];
    float knx2 = g_Kv[(size_t)idxs[2] * Hn + row];
    float thc  = ths[0];

    u64t M[32];
#pragma unroll
    for (int c = 0; c < 32; ++c) M[c] = 0ull;
    __syncthreads();

    // prologue: preload kn[0] into krA (slot 0 written before the bar above)
    u64t krA[32], krB[32];
    {
        const float4* nx = (const float4*)(kns[0] + 68 * half);
#pragma unroll
        for (int c = 0; c < 8; ++c) {
            float4 v0 = nx[2 * c];
            float4 v1 = nx[2 * c + 1];
            krA[4 * c]     = pk2(v0.x, v0.y);
            krA[4 * c + 1] = pk2(v0.z, v0.w);
            krA[4 * c + 2] = pk2(v1.x, v1.y);
            krA[4 * c + 3] = pk2(v1.z, v1.w);
        }
    }

    // 2046 steps as 1023 pairs, then step 2046 as epilogue
#pragma unroll 1
    for (int t0 = 0; t0 < Ln - 2; t0 += 2) {
        SCAN_STEP(t0,     krA, krB);
        SCAN_STEP(t0 + 1, krB, krA);
    }
    SCAN_STEP(Ln - 2, krA, krB);   // loads krB <- ring slot (Ln-1)&7 = raw q

    // ---- read = M @ q (q already in krB registers) ----
    {
        u64t a0 = 0ull, a1 = 0ull;
#pragma unroll
        for (int cc = 0; cc < 16; ++cc) {
            fma2(a0, M[2 * cc],     krB[2 * cc]);
            fma2(a1, M[2 * cc + 1], krB[2 * cc + 1]);
        }
        float vph = hsum(a0) + hsum(a1);
        float rd = vph + __shfl_xor_sync(0xffffffffu, vph, 1);
        if (half == 0) g_read[b * Hn + row] = rd;
    }
}

// ------------------------- K2b: r2 = read @ rp_w^T + rp_b ------------------
__global__ void k2b(const float* __restrict__ rpw, const float* __restrict__ rpb) {
    __shared__ __align__(16) float rs[128];
    const int b = blockIdx.x, tid = threadIdx.x;
    rs[tid] = g_read[b * Hn + tid];
    __syncthreads();
    const u64t* rp = (const u64t*)rs;
    u64t acc = 0ull;
#pragma unroll 8
    for (int j2 = 0; j2 < 64; ++j2) {
        u64t wv = *(const u64t*)(rpw + tid * 128 + 2 * j2);
        fma2(acc, rp[j2], wv);
    }
    g_r2[b * Hn + tid] = hsum(acc) + rpb[tid];
}

// ------------------------- K3: out = r2 @ out_w^T + out_b ------------------
#define K3_SMEM ((64 * 128 + 64 * 130) * 4)

__global__ __launch_bounds__(256, 1)
void k3(const float* __restrict__ ow, const float* __restrict__ ob,
        float* __restrict__ out) {
    extern __shared__ float sm[];
    float* r2s = sm;             // 64 x 128
    float* ws = sm + 64 * 128;   // 64 x 130

    const int tid = threadIdx.x;
    const int v0 = blockIdx.x * 64;

    for (int i = tid; i < 64 * 32; i += 256)
        ((float4*)r2s)[i] = ((const float4*)g_r2)[i];
    for (int i = tid; i < 64 * 64; i += 256) {
        int r = i >> 6, c = i & 63;
        *(float2*)(ws + r * 130 + 2 * c) = *(const float2*)(ow + (size_t)(v0 + r) * 128 + 2 * c);
    }
    __syncthreads();

    const int vl = tid & 63;
    const int bg = tid >> 6;
    const float obv = ob[v0 + vl];

#pragma unroll 4
    for (int bi = 0; bi < 16; ++bi) {
        int bb = bg * 16 + bi;
        u64t acc = 0ull;
#pragma unroll 16
        for (int h2 = 0; h2 < 64; ++h2)
            fma2(acc, *(const u64t*)(r2s + bb * 128 + 2 * h2),
                      *(const u64t*)(ws + vl * 130 + 2 * h2));
        out[(size_t)bb * Vn + v0 + vl] = hsum(acc) + obv;
    }
}

// ------------------------- launch ------------------------------------------
extern "C" void kernel_launch(void* const* d_in, const int* in_sizes, int n_in,
                              void* d_out, int out_size) {
    (void)in_sizes; (void)n_in; (void)out_size;
    const void*  seq = d_in[0];
    const float* ew  = (const float*)d_in[1];
    const float* w1  = (const float*)d_in[2];
    const float* b1  = (const float*)d_in[3];
    const float* w2  = (const float*)d_in[4];
    const float* b2  = (const float*)d_in[5];
    const float* lng = (const float*)d_in[6];
    const float* lnb = (const float*)d_in[7];
    const float* kpw = (const float*)d_in[8];
    const float* rpw = (const float*)d_in[9];
    const float* rpb = (const float*)d_in[10];
    const float* ow  = (const float*)d_in[11];
    const float* ob  = (const float*)d_in[12];
    float* out = (float*)d_out;

    cudaFuncSetAttribute(kv1,  cudaFuncAttributeMaxDynamicSharedMemorySize, KVT_SMEM);
    cudaFuncSetAttribute(kv2a, cudaFuncAttributeMaxDynamicSharedMemorySize, KVT_SMEM);
    cudaFuncSetAttribute(kv2b, cudaFuncAttributeMaxDynamicSharedMemorySize, KVT_SMEM);
    cudaFuncSetAttribute(kv3,  cudaFuncAttributeMaxDynamicSharedMemorySize, KVT_SMEM);
    cudaFuncSetAttribute(k3,   cudaFuncAttributeMaxDynamicSharedMemorySize, K3_SMEM);

    k0_detect<<<1, 256>>>((const unsigned int*)seq);
    kv1 <<<296, 256, KVT_SMEM>>>(ew, w1, b1, 0);
    kv1 <<<296, 256, KVT_SMEM>>>(ew, w1, b1, 128);
    kv2a<<<296, 256, KVT_SMEM>>>(w2);
    kv2b<<<296, 256, KVT_SMEM>>>(ew, w2, b2, lng, lnb);
    kv3 <<<296, 256, KVT_SMEM>>>(kpw);
    k2_scan<<<Bn, 256>>>(seq);
    k2b<<<Bn, 128>>>(rpw, rpb);
    k3<<<Vn / 64, 256, K3_SMEM>>>(ow, ob, out);
}